// round 16
// baseline (speedup 1.0000x reference)
#include <cuda_runtime.h>
#include <math.h>

#define TT 128
#define NB 256
#define OFF_ZF  0ull
#define OFF_PF  1048576ull
#define OFF_ZP  34603008ull
#define OFF_AF  35651584ull
#define OFF_AP  36175872ull
#define OFF_PP  36700160ull
#define OFF_ALP 70254592ull
#define OFF_AL  70516736ull
#define OFF_CL  104071168ull
#define OFF_ZM  120848384ull
#define OFF_LT  121896960ull
#define OFF_S   155451392ull

// parallel group = warps 0-5 + 7 (224 threads); chol group = all 256
#define B224 asm volatile("bar.sync 1, 224;" ::: "memory")
#define BAR3 asm volatile("bar.sync 3, 256;" ::: "memory")

__device__ float g_alpha[(size_t)NB * 129 * 8];
__device__ __align__(16) float g_C128[NB * 512];

__device__ __forceinline__ float sigmoidf_(float x){ return 1.0f/(1.0f+expf(-x)); }

__device__ __forceinline__ float dot32(const float* __restrict__ a, const float* __restrict__ b){
    float4 s0 = make_float4(0.f,0.f,0.f,0.f), s1 = s0;
    #pragma unroll
    for (int c = 0; c < 4; c++){
        float4 x0 = ((const float4*)a)[c],   y0 = ((const float4*)b)[c];
        float4 x1 = ((const float4*)a)[c+4], y1 = ((const float4*)b)[c+4];
        s0.x += x0.x*y0.x; s0.y += x0.y*y0.y; s0.z += x0.z*y0.z; s0.w += x0.w*y0.w;
        s1.x += x1.x*y1.x; s1.y += x1.y*y1.y; s1.z += x1.z*y1.z; s1.w += x1.w*y1.w;
    }
    return ((s0.x+s0.y)+(s0.z+s0.w)) + ((s1.x+s1.y)+(s1.z+s1.w));
}

// n in [0,144) -> lower-triangular float4 block (i, j4) of 32x32
__device__ __forceinline__ void low_map(int n, int& i, int& j4){
    int q = (int)((sqrtf(1.0f + 2.0f*(float)n) - 1.0f)*0.5f);
    while (2*(q+1)*(q+2) <= n) q++;
    while (2*q*(q+1) > n) q--;
    int m0 = n - 2*q*(q+1), g = q + 1;
    int rr = m0 / g;
    i = 4*q + rr;
    j4 = (m0 - rr*g)*4;
}

// ============ serial GRU chain (alphas only) — validated ============
__global__ __launch_bounds__(192)
void gru_kernel(const float* __restrict__ a_seq, const float* __restrict__ h_obs,
                const float* __restrict__ a0,    const float* __restrict__ Wx,
                const float* __restrict__ Wh,    const float* __restrict__ bb,
                const float* __restrict__ Wo,    const float* __restrict__ bo,
                float* __restrict__ out)
{
    __shared__ float av[16], hs[2][64], hn[64], gx[192], gh[192], hx[64], part[192];
    const int b = blockIdx.x, tid = threadIdx.x;
    {
        int c = tid >> 6, d = tid & 63;
        int t0 = c*43, t1 = (c==2) ? 128 : (t0+43);
        float s = 0.f;
        const float* hp = h_obs + ((size_t)b*TT + t0)*64 + d;
        for (int t = t0; t < t1; t++, hp += 64) s += *hp;
        part[tid] = s;
    }
    if (tid < 16) av[tid] = a0[tid];
    if (tid < 64) hs[0][tid] = 0.f;
    __syncthreads();
    if (tid < 64) hx[tid] = (part[tid]+part[64+tid]+part[128+tid])*(1.0f/128.0f);
    __syncthreads();
    float wxr[16], whr[64];
    #pragma unroll
    for (int i = 0; i < 16; i++) wxr[i] = Wx[i*192 + tid];
    #pragma unroll
    for (int d = 0; d < 64; d++) whr[d] = Wh[d*192 + tid];
    float gst = bb[tid];
    {
        float s0=0.f,s1=0.f,s2=0.f,s3=0.f;
        #pragma unroll
        for (int d = 0; d < 64; d += 4){
            s0 += hx[d]*Wx[(16+d)*192 + tid];   s1 += hx[d+1]*Wx[(17+d)*192 + tid];
            s2 += hx[d+2]*Wx[(18+d)*192 + tid]; s3 += hx[d+3]*Wx[(19+d)*192 + tid];
        }
        gst += (s0+s1)+(s2+s3);
    }
    for (int s = 0; s <= TT; s++){
        const float* hc = hs[s & 1];
        {
            float ga = gst, gb2 = 0.f;
            #pragma unroll
            for (int i = 0; i < 16; i += 2){ ga += av[i]*wxr[i]; gb2 += av[i+1]*wxr[i+1]; }
            gx[tid] = ga + gb2;
            float s0=0.f,s1=0.f,s2=0.f,s3=0.f;
            #pragma unroll
            for (int d = 0; d < 64; d += 4){
                s0 += hc[d]*whr[d];     s1 += hc[d+1]*whr[d+1];
                s2 += hc[d+2]*whr[d+2]; s3 += hc[d+3]*whr[d+3];
            }
            gh[tid] = (s0+s1)+(s2+s3);
        }
        __syncthreads();
        if (tid < 64){
            float r = sigmoidf_(gx[tid]       + gh[tid]);
            float u = sigmoidf_(gx[64 + tid]  + gh[64 + tid]);
            float n = tanhf   (gx[128 + tid] + r*gh[128 + tid]);
            float hv = (1.f - u)*n + u*hc[tid];
            hn[tid] = hv;
            hs[(s+1) & 1][tid] = hv;
        } else if (tid >= 176 && s < TT){
            av[tid-176] = a_seq[((size_t)b*TT + s)*16 + (tid-176)];
        }
        __syncthreads();
        if (tid < 32){
            int o = tid >> 2, seg = tid & 3;
            float l0 = 0.f, l1 = 0.f;
            #pragma unroll
            for (int q = 0; q < 16; q += 2){
                int d = seg*16 + q;
                l0 += hn[d]*Wo[d*8 + o];
                l1 += hn[d+1]*Wo[(d+1)*8 + o];
            }
            float lg = l0 + l1;
            lg += __shfl_xor_sync(0xffffffffu, lg, 1);
            lg += __shfl_xor_sync(0xffffffffu, lg, 2);
            lg += bo[o];
            float m = lg;
            #pragma unroll
            for (int st = 4; st < 32; st <<= 1) m = fmaxf(m, __shfl_xor_sync(0xffffffffu, m, st));
            float ev = expf(lg - m), sm = ev;
            #pragma unroll
            for (int st = 4; st < 32; st <<= 1) sm += __shfl_xor_sync(0xffffffffu, sm, st);
            float al = ev/sm;
            if (seg == 0){
                g_alpha[((size_t)b*129 + s)*8 + o] = al;
                if (s >= 1) out[OFF_ALP + ((size_t)b*TT + (s-1))*8 + o] = al;
            }
        }
    }
}

// ============ parallel mixtures — validated ============
__global__ __launch_bounds__(192)
void mix_kernel(const float* __restrict__ Amat, const float* __restrict__ Cmat,
                float* __restrict__ out)
{
    const int b = blockIdx.x, s = blockIdx.y, tid = threadIdx.x;
    __shared__ float al[8];
    if (tid < 8) al[tid] = g_alpha[((size_t)b*129 + s)*8 + tid];
    __syncthreads();
    if (s >= 1){
        #pragma unroll
        for (int r = 0; r < 6; r++){
            int e = tid + 192*r;
            if (e < 1024){
                float v = 0.f;
                #pragma unroll
                for (int k = 0; k < 8; k++) v += al[k]*Amat[k*1024 + e];
                out[OFF_AL + ((size_t)b*TT + (s-1))*1024 + e] = v;
            }
        }
    }
    #pragma unroll
    for (int r = 0; r < 3; r++){
        int e = tid + 192*r;
        if (e < 512){
            float v = 0.f;
            #pragma unroll
            for (int k = 0; k < 8; k++) v += al[k]*Cmat[k*512 + e];
            if (s <= 127) out[OFF_CL + ((size_t)b*TT + s)*512 + e] = v;
            else          g_C128[b*512 + e] = v;
        }
    }
}

// ============ main Kalman kernel: 7-warp parallel group (0-5,7), chol on warp 6 ============
__global__ __launch_bounds__(256, 2)
void kf_kernel(const float* __restrict__ a_seq, float* __restrict__ out)
{
    __shared__ __align__(16) float P[1152], PfD[2][1152], Xb[1152], As[1152], AsT[1152];
    __shared__ __align__(16) float Cb[2][576], CP[576], Wb[576], SG[320];
    __shared__ __align__(16) float zn[32], zfn[32], rvec[16], srv[16];

    const int tid = threadIdx.x, wid = tid >> 5, lane = tid & 31;
    const int b = blockIdx.x;
    const int lt = (tid >= 224) ? (tid - 32) : tid;   // warp7 -> 192..223

    int lmi = 0, lmj4 = 0;
    if (tid < 144) low_map(tid, lmi, lmj4);

    if (tid < 32) zn[tid] = 0.f;
    #pragma unroll
    for (int k = 0; k < 4; k++){
        int e = tid + 256*k, i = e >> 5, j = e & 31;
        P[i*36 + j] = (i == j) ? 10.f : 0.f;
    }
    if (tid < 128){
        int e = tid*4, i = e >> 5, j = e & 31;
        *(float4*)&Cb[0][i*36 + j] = *(const float4*)(out + OFF_CL + (size_t)b*TT*512 + e);
    }
    __syncthreads();

    if (wid != 6){
        for (int t = 0; t < TT; t++){
            const size_t bt = (size_t)b*TT + t;
            const float* Ct = Cb[t&1];
            const float* Cn = Cb[(t+1)&1];
            float* Pfc = PfD[t & 1];

            // phA: CP = C_t * P (lt<128) || prefetch A_{t+1}->As,AsT ; C_{t+1}->Cn (96 thr)
            if (lt < 128){
                int i = lt >> 3, j4 = (lt & 7)*4;
                float4 a0 = make_float4(0,0,0,0), a1 = a0;
                #pragma unroll
                for (int m = 0; m < 16; m++){
                    float c0 = Ct[i*36 + m], c1 = Ct[i*36 + m + 16];
                    float4 p0 = *(const float4*)(P + m*36 + j4);
                    float4 p1 = *(const float4*)(P + (m+16)*36 + j4);
                    a0.x += c0*p0.x; a0.y += c0*p0.y; a0.z += c0*p0.z; a0.w += c0*p0.w;
                    a1.x += c1*p1.x; a1.y += c1*p1.y; a1.z += c1*p1.z; a1.w += c1*p1.w;
                }
                a0.x += a1.x; a0.y += a1.y; a0.z += a1.z; a0.w += a1.w;
                *(float4*)&CP[i*36 + j4] = a0;
            } else {
                int idx = lt - 128;   // 0..95
                #pragma unroll
                for (int r = 0; r < 4; r++){
                    int n4 = idx + 96*r;
                    if (n4 < 256){
                        int e = n4*4, i = e >> 5, j = e & 31;
                        float4 g = *(const float4*)(out + OFF_AL + bt*1024 + e);
                        *(float4*)&As[i*36 + j] = g;
                        AsT[(j+0)*36+i] = g.x; AsT[(j+1)*36+i] = g.y;
                        AsT[(j+2)*36+i] = g.z; AsT[(j+3)*36+i] = g.w;
                    } else {
                        int e = (n4 - 256)*4, i = e >> 5, j = e & 31;
                        float4 g = (t < 127) ? *(const float4*)(out + OFF_CL + (bt+1)*512 + e)
                                             : *(const float4*)(g_C128 + b*512 + e);
                        *(float4*)&Cb[(t+1)&1][i*36 + j] = g;
                    }
                }
            }
            B224;

            // phB: S on 128 threads (2 elements each, dot form) ; rvec on 128-143
            if (lt < 128){
                int i0 = lt >> 4, j0 = lt & 15;
                float sv0 = dot32(CP + i0*36, Ct + j0*36) + ((i0==j0)?0.3f:0.f);
                SG[i0*20 + j0] = sv0;
                out[OFF_S + bt*256 + lt] = sv0;
                int n1 = lt + 128;
                int i1 = n1 >> 4, j1 = n1 & 15;
                float sv1 = dot32(CP + i1*36, Ct + j1*36) + ((i1==j1)?0.3f:0.f);
                SG[i1*20 + j1] = sv1;
                out[OFF_S + bt*256 + n1] = sv1;
            } else if (lt < 144){
                int la = lt - 128;
                rvec[la] = a_seq[bt*16 + la] - dot32(Ct + la*36, zn);
            }
            B224;   // GJ entry

            // ---- window: warp 7 GJ ; warps 0-5 deferred PF/PP stores of t-1 ----
            if (wid == 7){
                float c[16], d[16];
                #pragma unroll
                for (int i = 0; i < 16; i++){
                    c[i] = (lane < 16) ? SG[i*20 + lane] : ((lane == 16) ? rvec[i] : 0.f);
                    d[i] = CP[i*36 + lane];
                }
                #pragma unroll
                for (int p = 0; p < 16; p++){
                    float piv = __shfl_sync(0xffffffffu, c[p], p);
                    float inv = __fdividef(1.0f, piv);
                    float pc = c[p]*inv, pd = d[p]*inv;
                    #pragma unroll
                    for (int i = 0; i < 16; i++){
                        if (i == p) continue;
                        float fc = __shfl_sync(0xffffffffu, c[i], p);
                        c[i] -= fc*pc; d[i] -= fc*pd;
                    }
                    c[p] = pc; d[p] = pd;
                }
                #pragma unroll
                for (int i = 0; i < 16; i++) Wb[i*36 + lane] = d[i];
                if (lane == 16){
                    #pragma unroll
                    for (int i = 0; i < 16; i++) srv[i] = c[i];
                }
            } else if (t > 0){
                const size_t bp = bt - 1;
                const float* Pfp = PfD[(t-1)&1];
                #pragma unroll
                for (int k = 0; k < 2; k++){
                    int n4 = lt + 192*k;
                    if (n4 < 256){
                        int e = n4*4, i = e >> 5, j = e & 31;
                        *(float4*)(out + OFF_PF + bp*1024 + e) = *(const float4*)&Pfp[i*36 + j];
                        *(float4*)(out + OFF_PP + bp*1024 + e) = *(const float4*)&P[i*36 + j];
                    }
                }
            }
            B224;   // GJ done: Wb, srv ready

            // phE: X = lower(CP^T W) -> Xb (lt<144) ; zfn on warp 7 (lt 192..223)
            if (lt < 144){
                int i = lmi, j4 = lmj4;
                float4 a0v = make_float4(0,0,0,0), a1v = a0v;
                #pragma unroll
                for (int m = 0; m < 8; m++){
                    float c0 = CP[m*36 + i], c1 = CP[(m+8)*36 + i];
                    float4 w0 = *(const float4*)(Wb + m*36 + j4);
                    float4 w1 = *(const float4*)(Wb + (m+8)*36 + j4);
                    a0v.x += c0*w0.x; a0v.y += c0*w0.y; a0v.z += c0*w0.z; a0v.w += c0*w0.w;
                    a1v.x += c1*w1.x; a1v.y += c1*w1.y; a1v.z += c1*w1.z; a1v.w += c1*w1.w;
                }
                a0v.x += a1v.x; a0v.y += a1v.y; a0v.z += a1v.z; a0v.w += a1v.w;
                *(float4*)&Xb[i*36 + j4] = a0v;
            } else if (lt >= 192){
                int la = lt - 192;
                float s0 = zn[la], s1 = 0.f;
                #pragma unroll
                for (int m = 0; m < 8; m++){
                    s0 += CP[m*36 + la]*srv[m];
                    s1 += CP[(m+8)*36 + la]*srv[m+8];
                }
                zfn[la] = s0 + s1;
            }
            B224;

            // phF: Pf = P - X (mirror upper) -> PfD[t&1] ; vec outputs
            #pragma unroll
            for (int r = 0; r < 2; r++){
                int T = lt + 224*r;
                if (T < 256){
                    int i = T >> 3, j4 = (T & 7)*4;
                    float4 p4 = *(const float4*)&P[i*36 + j4];
                    float4 x4;
                    if (j4 <= i) x4 = *(const float4*)&Xb[i*36 + j4];
                    else { x4.x = Xb[(j4+0)*36+i]; x4.y = Xb[(j4+1)*36+i];
                           x4.z = Xb[(j4+2)*36+i]; x4.w = Xb[(j4+3)*36+i]; }
                    float4 pf4 = make_float4(p4.x-x4.x, p4.y-x4.y, p4.z-x4.z, p4.w-x4.w);
                    *(float4*)&Pfc[i*36 + j4] = pf4;
                } else if (T < 336){
                    int idx = T - 256;
                    if (idx < 32){
                        float zp = dot32(As + idx*36, zfn);
                        zn[idx] = zp;
                        out[OFF_ZP + bt*32 + idx] = zp;
                    } else if (idx < 48){
                        out[OFF_AF + bt*16 + (idx-32)] = dot32(Ct + (idx-32)*36, zfn);
                    } else {
                        float z = zfn[idx-48];
                        out[OFF_ZF + bt*32 + (idx-48)] = z;
                        out[OFF_ZM + bt*32 + (idx-48)] = z;
                    }
                }
            }
            BAR3;   // chol (warp 6) enters on PfD[t&1]

            // phG: M2 = A_{t+1} * Pf  (into Xb, full)
            #pragma unroll
            for (int r = 0; r < 2; r++){
                int T = lt + 224*r;
                if (T < 256){
                    int i = T >> 3, j4 = (T & 7)*4;
                    float4 a0v = make_float4(0,0,0,0), a1v = a0v;
                    #pragma unroll
                    for (int m = 0; m < 16; m++){
                        float c0 = As[i*36 + m], c1 = As[i*36 + m + 16];
                        float4 p0 = *(const float4*)(Pfc + m*36 + j4);
                        float4 p1 = *(const float4*)(Pfc + (m+16)*36 + j4);
                        a0v.x += c0*p0.x; a0v.y += c0*p0.y; a0v.z += c0*p0.z; a0v.w += c0*p0.w;
                        a1v.x += c1*p1.x; a1v.y += c1*p1.y; a1v.z += c1*p1.z; a1v.w += c1*p1.w;
                    }
                    a0v.x += a1v.x; a0v.y += a1v.y; a0v.z += a1v.z; a0v.w += a1v.w;
                    *(float4*)&Xb[i*36 + j4] = a0v;
                }
            }
            B224;

            // phH: P = M2*A^T + Q direct (lower blocks + mirror) ; a_pred
            if (lt < 144){
                int i = lmi, j4 = lmj4;
                float4 a0v = make_float4(0,0,0,0), a1v = a0v;
                #pragma unroll
                for (int m = 0; m < 16; m++){
                    float c0 = Xb[i*36 + m], c1 = Xb[i*36 + m + 16];
                    float4 t0 = *(const float4*)(AsT + m*36 + j4);
                    float4 t1 = *(const float4*)(AsT + (m+16)*36 + j4);
                    a0v.x += c0*t0.x; a0v.y += c0*t0.y; a0v.z += c0*t0.z; a0v.w += c0*t0.w;
                    a1v.x += c1*t1.x; a1v.y += c1*t1.y; a1v.z += c1*t1.z; a1v.w += c1*t1.w;
                }
                a0v.x += a1v.x; a0v.y += a1v.y; a0v.z += a1v.z; a0v.w += a1v.w;
                if (j4 + 3 < i){
                    *(float4*)&P[i*36 + j4] = a0v;
                    P[(j4+0)*36 + i] = a0v.x; P[(j4+1)*36 + i] = a0v.y;
                    P[(j4+2)*36 + i] = a0v.z; P[(j4+3)*36 + i] = a0v.w;
                } else {
                    float v[4] = {a0v.x, a0v.y, a0v.z, a0v.w};
                    #pragma unroll
                    for (int k = 0; k < 4; k++){
                        int jj = j4 + k;
                        if (jj < i){ P[i*36 + jj] = v[k]; P[jj*36 + i] = v[k]; }
                        else if (jj == i) P[i*36 + jj] = v[k] + 0.2f;
                    }
                }
            } else if (lt >= 160 && lt < 176){
                int la = lt - 160;
                out[OFF_AP + bt*16 + la] = dot32(Cn + la*36, zn);
            }
            B224;
        }
    } else {
        // warp 6: register Cholesky of Pf (+jitter), stores L directly
        for (int t = 0; t < TT; t++){
            BAR3;
            const float* Pfc = PfD[t&1];
            float a[32];
            #pragma unroll
            for (int c = 0; c < 8; c++){
                float4 v = *(const float4*)(Pfc + lane*36 + c*4);
                a[c*4] = v.x; a[c*4+1] = v.y; a[c*4+2] = v.z; a[c*4+3] = v.w;
            }
            a[lane] += 2e-4f;
            float* o = out + OFF_LT + ((size_t)b*TT + t)*1024 + lane*32;
            #pragma unroll
            for (int j = 0; j < 32; j++){
                float d = __shfl_sync(0xffffffffu, a[j], j);
                float lij = a[j] * rsqrtf(d);
                o[j] = (lane >= j) ? lij : 0.f;
                #pragma unroll
                for (int k = j+1; k < 32; k++)
                    a[k] -= lij * __shfl_sync(0xffffffffu, lij, k);
            }
        }
    }

    __syncthreads();
    // epilogue: PF/PP for t = 127
    const size_t bl = (size_t)b*TT + 127;
    {
        int e = tid*4, i = e >> 5, j = e & 31;
        *(float4*)(out + OFF_PF + bl*1024 + e) = *(const float4*)&PfD[1][i*36 + j];
        *(float4*)(out + OFF_PP + bl*1024 + e) = *(const float4*)&P[i*36 + j];
    }
}

extern "C" void kernel_launch(void* const* d_in, const int* in_sizes, int n_in,
                              void* d_out, int out_size) {
    const float* a_seq = (const float*)d_in[0];
    const float* h_obs = (const float*)d_in[1];
    const float* Amat  = (const float*)d_in[2];
    const float* Cmat  = (const float*)d_in[3];
    const float* a0    = (const float*)d_in[4];
    const float* Wx    = (const float*)d_in[5];
    const float* Wh    = (const float*)d_in[6];
    const float* bb    = (const float*)d_in[7];
    const float* Wo    = (const float*)d_in[8];
    const float* bo    = (const float*)d_in[9];
    float* out = (float*)d_out;

    gru_kernel<<<NB, 192>>>(a_seq, h_obs, a0, Wx, Wh, bb, Wo, bo, out);
    mix_kernel<<<dim3(NB, 129), 192>>>(Amat, Cmat, out);
    kf_kernel<<<NB, 256>>>(a_seq, out);
}

// round 17
// speedup vs baseline: 1.1031x; 1.1031x over previous
#include <cuda_runtime.h>
#include <math.h>

#define TT 128
#define NB 256
#define OFF_ZF  0ull
#define OFF_PF  1048576ull
#define OFF_ZP  34603008ull
#define OFF_AF  35651584ull
#define OFF_AP  36175872ull
#define OFF_PP  36700160ull
#define OFF_ALP 70254592ull
#define OFF_AL  70516736ull
#define OFF_CL  104071168ull
#define OFF_ZM  120848384ull
#define OFF_LT  121896960ull
#define OFF_S   155451392ull

#define BAR1 asm volatile("bar.sync 1, 192;" ::: "memory")
#define BAR2 asm volatile("bar.sync 2, 224;" ::: "memory")
#define BAR3 asm volatile("bar.sync 3, 224;" ::: "memory")

__device__ float g_alpha[(size_t)NB * 129 * 8];
__device__ __align__(16) float g_C128[NB * 512];

__device__ __forceinline__ float sigmoidf_(float x){ return 1.0f/(1.0f+expf(-x)); }

__device__ __forceinline__ float dot32(const float* __restrict__ a, const float* __restrict__ b){
    float4 s0 = make_float4(0.f,0.f,0.f,0.f), s1 = s0;
    #pragma unroll
    for (int c = 0; c < 4; c++){
        float4 x0 = ((const float4*)a)[c],   y0 = ((const float4*)b)[c];
        float4 x1 = ((const float4*)a)[c+4], y1 = ((const float4*)b)[c+4];
        s0.x += x0.x*y0.x; s0.y += x0.y*y0.y; s0.z += x0.z*y0.z; s0.w += x0.w*y0.w;
        s1.x += x1.x*y1.x; s1.y += x1.y*y1.y; s1.z += x1.z*y1.z; s1.w += x1.w*y1.w;
    }
    return ((s0.x+s0.y)+(s0.z+s0.w)) + ((s1.x+s1.y)+(s1.z+s1.w));
}

// n in [0,144) -> lower-triangular float4 block (i, j4) of 32x32
__device__ __forceinline__ void low_map(int n, int& i, int& j4){
    int q = (int)((sqrtf(1.0f + 2.0f*(float)n) - 1.0f)*0.5f);
    while (2*(q+1)*(q+2) <= n) q++;
    while (2*q*(q+1) > n) q--;
    int m0 = n - 2*q*(q+1), g = q + 1;
    int rr = m0 / g;
    i = 4*q + rr;
    j4 = (m0 - rr*g)*4;
}

// ============ serial GRU chain (alphas only) — 32-lane logits (validated 136us) ============
__global__ __launch_bounds__(192)
void gru_kernel(const float* __restrict__ a_seq, const float* __restrict__ h_obs,
                const float* __restrict__ a0,    const float* __restrict__ Wx,
                const float* __restrict__ Wh,    const float* __restrict__ bb,
                const float* __restrict__ Wo,    const float* __restrict__ bo,
                float* __restrict__ out)
{
    __shared__ float av[16], hs[2][64], hn[64], gx[192], gh[192], hx[64], part[192];
    const int b = blockIdx.x, tid = threadIdx.x;
    {
        int c = tid >> 6, d = tid & 63;
        int t0 = c*43, t1 = (c==2) ? 128 : (t0+43);
        float s = 0.f;
        const float* hp = h_obs + ((size_t)b*TT + t0)*64 + d;
        for (int t = t0; t < t1; t++, hp += 64) s += *hp;
        part[tid] = s;
    }
    if (tid < 16) av[tid] = a0[tid];
    if (tid < 64) hs[0][tid] = 0.f;
    __syncthreads();
    if (tid < 64) hx[tid] = (part[tid]+part[64+tid]+part[128+tid])*(1.0f/128.0f);
    __syncthreads();
    float wxr[16], whr[64];
    #pragma unroll
    for (int i = 0; i < 16; i++) wxr[i] = Wx[i*192 + tid];
    #pragma unroll
    for (int d = 0; d < 64; d++) whr[d] = Wh[d*192 + tid];
    float gst = bb[tid];
    {
        float s0=0.f,s1=0.f,s2=0.f,s3=0.f;
        #pragma unroll
        for (int d = 0; d < 64; d += 4){
            s0 += hx[d]*Wx[(16+d)*192 + tid];   s1 += hx[d+1]*Wx[(17+d)*192 + tid];
            s2 += hx[d+2]*Wx[(18+d)*192 + tid]; s3 += hx[d+3]*Wx[(19+d)*192 + tid];
        }
        gst += (s0+s1)+(s2+s3);
    }
    for (int s = 0; s <= TT; s++){
        const float* hc = hs[s & 1];
        {
            float ga = gst, gb2 = 0.f;
            #pragma unroll
            for (int i = 0; i < 16; i += 2){ ga += av[i]*wxr[i]; gb2 += av[i+1]*wxr[i+1]; }
            gx[tid] = ga + gb2;
            float s0=0.f,s1=0.f,s2=0.f,s3=0.f;
            #pragma unroll
            for (int d = 0; d < 64; d += 4){
                s0 += hc[d]*whr[d];     s1 += hc[d+1]*whr[d+1];
                s2 += hc[d+2]*whr[d+2]; s3 += hc[d+3]*whr[d+3];
            }
            gh[tid] = (s0+s1)+(s2+s3);
        }
        __syncthreads();
        if (tid < 64){
            float r = sigmoidf_(gx[tid]       + gh[tid]);
            float u = sigmoidf_(gx[64 + tid]  + gh[64 + tid]);
            float n = tanhf   (gx[128 + tid] + r*gh[128 + tid]);
            float hv = (1.f - u)*n + u*hc[tid];
            hn[tid] = hv;
            hs[(s+1) & 1][tid] = hv;
        } else if (tid >= 176 && s < TT){
            av[tid-176] = a_seq[((size_t)b*TT + s)*16 + (tid-176)];
        }
        __syncthreads();
        if (tid < 32){
            int o = tid >> 2, seg = tid & 3;
            float l0 = 0.f, l1 = 0.f;
            #pragma unroll
            for (int q = 0; q < 16; q += 2){
                int d = seg*16 + q;
                l0 += hn[d]*Wo[d*8 + o];
                l1 += hn[d+1]*Wo[(d+1)*8 + o];
            }
            float lg = l0 + l1;
            lg += __shfl_xor_sync(0xffffffffu, lg, 1);
            lg += __shfl_xor_sync(0xffffffffu, lg, 2);
            lg += bo[o];
            float m = lg;
            #pragma unroll
            for (int st = 4; st < 32; st <<= 1) m = fmaxf(m, __shfl_xor_sync(0xffffffffu, m, st));
            float ev = expf(lg - m), sm = ev;
            #pragma unroll
            for (int st = 4; st < 32; st <<= 1) sm += __shfl_xor_sync(0xffffffffu, sm, st);
            float al = ev/sm;
            if (seg == 0){
                g_alpha[((size_t)b*129 + s)*8 + o] = al;
                if (s >= 1) out[OFF_ALP + ((size_t)b*TT + (s-1))*8 + o] = al;
            }
        }
    }
}

// ============ parallel mixtures ============
__global__ __launch_bounds__(192)
void mix_kernel(const float* __restrict__ Amat, const float* __restrict__ Cmat,
                float* __restrict__ out)
{
    const int b = blockIdx.x, s = blockIdx.y, tid = threadIdx.x;
    __shared__ float al[8];
    if (tid < 8) al[tid] = g_alpha[((size_t)b*129 + s)*8 + tid];
    __syncthreads();
    if (s >= 1){
        #pragma unroll
        for (int r = 0; r < 6; r++){
            int e = tid + 192*r;
            if (e < 1024){
                float v = 0.f;
                #pragma unroll
                for (int k = 0; k < 8; k++) v += al[k]*Amat[k*1024 + e];
                out[OFF_AL + ((size_t)b*TT + (s-1))*1024 + e] = v;
            }
        }
    }
    #pragma unroll
    for (int r = 0; r < 3; r++){
        int e = tid + 192*r;
        if (e < 512){
            float v = 0.f;
            #pragma unroll
            for (int k = 0; k < 8; k++) v += al[k]*Cmat[k*512 + e];
            if (s <= 127) out[OFF_CL + ((size_t)b*TT + s)*512 + e] = v;
            else          g_C128[b*512 + e] = v;
        }
    }
}

// ============ main Kalman kernel (round-10 verbatim: 6 par warps + chol + GJ) ============
__global__ __launch_bounds__(256, 2)
void kf_kernel(const float* __restrict__ a_seq, float* __restrict__ out)
{
    __shared__ __align__(16) float P[1152], Pf[1152], Xb[1152], As[1152], AsT[1152];
    __shared__ __align__(16) float CHd[2][1152];
    __shared__ __align__(16) float Cb[2][576], CtT[2][640], CP[576], Wb[576], SG[320];
    __shared__ __align__(16) float zn[32], zfn[32], rvec[16], srv[16];

    const int tid = threadIdx.x, wid = tid >> 5, lane = tid & 31;
    const int b = blockIdx.x;

    int lmi = 0, lmj4 = 0;
    if (tid < 144) low_map(tid, lmi, lmj4);

    if (tid < 32) zn[tid] = 0.f;
    #pragma unroll
    for (int k = 0; k < 4; k++){
        int e = tid + 256*k, i = e >> 5, j = e & 31;
        P[i*36 + j] = (i == j) ? 10.f : 0.f;
    }
    if (tid < 128){
        int e = tid*4, i = e >> 5, j = e & 31;
        float4 g = *(const float4*)(out + OFF_CL + (size_t)b*TT*512 + e);
        *(float4*)&Cb[0][i*36 + j] = g;
        CtT[0][(j+0)*20+i] = g.x; CtT[0][(j+1)*20+i] = g.y;
        CtT[0][(j+2)*20+i] = g.z; CtT[0][(j+3)*20+i] = g.w;
    }
    __syncthreads();

    if (wid < 6){
        for (int t = 0; t < TT; t++){
            const size_t bt = (size_t)b*TT + t;
            float* Ct = Cb[t&1];  float* Cn = Cb[(t+1)&1];
            float* CtTc = CtT[t&1]; float* CtTn = CtT[(t+1)&1];
            float* CHc = CHd[t&1];

            // phA: CP = C_t * P (128) || prefetch A_{t+1}(+AsT), C_{t+1}(+CtTn) (64)
            if (tid < 128){
                int i = tid >> 3, j4 = (tid & 7)*4;
                float4 a0 = make_float4(0,0,0,0), a1 = a0;
                #pragma unroll
                for (int m = 0; m < 16; m++){
                    float c0 = Ct[i*36 + m], c1 = Ct[i*36 + m + 16];
                    float4 p0 = *(const float4*)(P + m*36 + j4);
                    float4 p1 = *(const float4*)(P + (m+16)*36 + j4);
                    a0.x += c0*p0.x; a0.y += c0*p0.y; a0.z += c0*p0.z; a0.w += c0*p0.w;
                    a1.x += c1*p1.x; a1.y += c1*p1.y; a1.z += c1*p1.z; a1.w += c1*p1.w;
                }
                a0.x += a1.x; a0.y += a1.y; a0.z += a1.z; a0.w += a1.w;
                *(float4*)&CP[i*36 + j4] = a0;
            } else {
                int idx = tid - 128;
                #pragma unroll
                for (int r = 0; r < 6; r++){
                    int n4 = idx + 64*r;
                    if (n4 < 256){
                        int e = n4*4, i = e >> 5, j = e & 31;
                        float4 g = *(const float4*)(out + OFF_AL + bt*1024 + e);
                        *(float4*)&As[i*36 + j] = g;
                        AsT[(j+0)*36+i] = g.x; AsT[(j+1)*36+i] = g.y;
                        AsT[(j+2)*36+i] = g.z; AsT[(j+3)*36+i] = g.w;
                    } else {
                        int e = (n4 - 256)*4, i = e >> 5, j = e & 31;
                        float4 g = (t < 127) ? *(const float4*)(out + OFF_CL + (bt+1)*512 + e)
                                             : *(const float4*)(g_C128 + b*512 + e);
                        *(float4*)&Cb[(t+1)&1][i*36 + j] = g;
                        CtTn[(j+0)*20+i] = g.x; CtTn[(j+1)*20+i] = g.y;
                        CtTn[(j+2)*20+i] = g.z; CtTn[(j+3)*20+i] = g.w;
                    }
                }
            }
            BAR1;

            // phB: S = CP*Ct^T + 0.3I (broadcast via CtT) ; rvec
            if (tid < 64){
                int i = tid >> 2, j4 = (tid & 3)*4;
                float4 a0 = make_float4(0,0,0,0), a1 = a0;
                #pragma unroll
                for (int m = 0; m < 16; m++){
                    float c0 = CP[i*36 + m], c1 = CP[i*36 + m + 16];
                    float4 t0 = *(const float4*)(CtTc + m*20 + j4);
                    float4 t1 = *(const float4*)(CtTc + (m+16)*20 + j4);
                    a0.x += c0*t0.x; a0.y += c0*t0.y; a0.z += c0*t0.z; a0.w += c0*t0.w;
                    a1.x += c1*t1.x; a1.y += c1*t1.y; a1.z += c1*t1.z; a1.w += c1*t1.w;
                }
                a0.x += a1.x; a0.y += a1.y; a0.z += a1.z; a0.w += a1.w;
                if (j4+0 == i) a0.x += 0.3f;
                if (j4+1 == i) a0.y += 0.3f;
                if (j4+2 == i) a0.z += 0.3f;
                if (j4+3 == i) a0.w += 0.3f;
                *(float4*)&SG[i*20 + j4] = a0;
                *(float4*)(out + OFF_S + bt*256 + i*16 + j4) = a0;
            } else if (tid < 80){
                int la = tid - 64;
                rvec[la] = a_seq[bt*16 + la] - dot32(Ct + la*36, zn);
            }
            BAR2;   // GJ (warp 7) enters

            // phC: deferred PF/PP stores of t-1 (fills GJ window)
            if (t > 0){
                const size_t bp = bt - 1;
                #pragma unroll
                for (int k = 0; k < 2; k++){
                    int n4 = tid + 192*k;
                    if (n4 < 256){
                        int e = n4*4, i = e >> 5, j = e & 31;
                        *(float4*)(out + OFF_PF + bp*1024 + e) = *(const float4*)&Pf[i*36 + j];
                        *(float4*)(out + OFF_PP + bp*1024 + e) = *(const float4*)&P[i*36 + j];
                    }
                }
            }
            BAR2;   // GJ done: Wb, srv ready

            // phE: X = lower(CP^T W) -> Xb ; zfn
            if (tid < 144){
                int i = lmi, j4 = lmj4;
                float4 a0v = make_float4(0,0,0,0), a1v = a0v;
                #pragma unroll
                for (int m = 0; m < 8; m++){
                    float c0 = CP[m*36 + i], c1 = CP[(m+8)*36 + i];
                    float4 w0 = *(const float4*)(Wb + m*36 + j4);
                    float4 w1 = *(const float4*)(Wb + (m+8)*36 + j4);
                    a0v.x += c0*w0.x; a0v.y += c0*w0.y; a0v.z += c0*w0.z; a0v.w += c0*w0.w;
                    a1v.x += c1*w1.x; a1v.y += c1*w1.y; a1v.z += c1*w1.z; a1v.w += c1*w1.w;
                }
                a0v.x += a1v.x; a0v.y += a1v.y; a0v.z += a1v.z; a0v.w += a1v.w;
                *(float4*)&Xb[i*36 + j4] = a0v;
            } else if (tid >= 160){
                int la = tid - 160;
                float s0 = zn[la], s1 = 0.f;
                #pragma unroll
                for (int m = 0; m < 8; m++){
                    s0 += CP[m*36 + la]*srv[m];
                    s1 += CP[(m+8)*36 + la]*srv[m+8];
                }
                zfn[la] = s0 + s1;
            }
            BAR1;

            // phF: Pf = P - X (mirror upper); CH = Pf + jitter; vec outputs
            #pragma unroll
            for (int r = 0; r < 2; r++){
                int T = tid + 192*r;
                if (T < 256){
                    int i = T >> 3, j4 = (T & 7)*4;
                    float4 p4 = *(const float4*)&P[i*36 + j4];
                    float4 x4;
                    if (j4 <= i) x4 = *(const float4*)&Xb[i*36 + j4];
                    else { x4.x = Xb[(j4+0)*36+i]; x4.y = Xb[(j4+1)*36+i];
                           x4.z = Xb[(j4+2)*36+i]; x4.w = Xb[(j4+3)*36+i]; }
                    float4 pf4 = make_float4(p4.x-x4.x, p4.y-x4.y, p4.z-x4.z, p4.w-x4.w);
                    *(float4*)&Pf[i*36 + j4] = pf4;
                    if (j4+0 == i) pf4.x += 2e-4f;
                    if (j4+1 == i) pf4.y += 2e-4f;
                    if (j4+2 == i) pf4.z += 2e-4f;
                    if (j4+3 == i) pf4.w += 2e-4f;
                    *(float4*)&CHc[i*36 + j4] = pf4;
                } else {
                    int idx = T - 256;
                    if (idx < 32){
                        float zp = dot32(As + idx*36, zfn);
                        zn[idx] = zp;                       // carry: z_pred
                        out[OFF_ZP + bt*32 + idx] = zp;
                    } else if (idx < 48){
                        out[OFF_AF + bt*16 + (idx-32)] = dot32(Ct + (idx-32)*36, zfn);
                    } else if (idx < 80){
                        float z = zfn[idx-48];
                        out[OFF_ZF + bt*32 + (idx-48)] = z;
                        out[OFF_ZM + bt*32 + (idx-48)] = z;
                    }
                }
            }
            BAR3;   // chol (warp 6) enters on CHc

            // phG: M2 = A_{t+1} * Pf  (into Xb, full)
            #pragma unroll
            for (int r = 0; r < 2; r++){
                int T = tid + 192*r;
                if (T < 256){
                    int i = T >> 3, j4 = (T & 7)*4;
                    float4 a0v = make_float4(0,0,0,0), a1v = a0v;
                    #pragma unroll
                    for (int m = 0; m < 16; m++){
                        float c0 = As[i*36 + m], c1 = As[i*36 + m + 16];
                        float4 p0 = *(const float4*)(Pf + m*36 + j4);
                        float4 p1 = *(const float4*)(Pf + (m+16)*36 + j4);
                        a0v.x += c0*p0.x; a0v.y += c0*p0.y; a0v.z += c0*p0.z; a0v.w += c0*p0.w;
                        a1v.x += c1*p1.x; a1v.y += c1*p1.y; a1v.z += c1*p1.z; a1v.w += c1*p1.w;
                    }
                    a0v.x += a1v.x; a0v.y += a1v.y; a0v.z += a1v.z; a0v.w += a1v.w;
                    *(float4*)&Xb[i*36 + j4] = a0v;
                }
            }
            BAR1;

            // phH (merged): P = M2*A^T + Q written directly (lower blocks + mirror) ; a_pred
            if (tid < 144){
                int i = lmi, j4 = lmj4;
                float4 a0v = make_float4(0,0,0,0), a1v = a0v;
                #pragma unroll
                for (int m = 0; m < 16; m++){
                    float c0 = Xb[i*36 + m], c1 = Xb[i*36 + m + 16];
                    float4 t0 = *(const float4*)(AsT + m*36 + j4);
                    float4 t1 = *(const float4*)(AsT + (m+16)*36 + j4);
                    a0v.x += c0*t0.x; a0v.y += c0*t0.y; a0v.z += c0*t0.z; a0v.w += c0*t0.w;
                    a1v.x += c1*t1.x; a1v.y += c1*t1.y; a1v.z += c1*t1.z; a1v.w += c1*t1.w;
                }
                a0v.x += a1v.x; a0v.y += a1v.y; a0v.z += a1v.z; a0v.w += a1v.w;
                if (j4 + 3 < i){
                    *(float4*)&P[i*36 + j4] = a0v;
                    P[(j4+0)*36 + i] = a0v.x; P[(j4+1)*36 + i] = a0v.y;
                    P[(j4+2)*36 + i] = a0v.z; P[(j4+3)*36 + i] = a0v.w;
                } else {
                    float v[4] = {a0v.x, a0v.y, a0v.z, a0v.w};
                    #pragma unroll
                    for (int k = 0; k < 4; k++){
                        int jj = j4 + k;
                        if (jj < i){ P[i*36 + jj] = v[k]; P[jj*36 + i] = v[k]; }
                        else if (jj == i) P[i*36 + jj] = v[k] + 0.2f;
                    }
                }
            } else if (tid >= 160 && tid < 176){
                int la = tid - 160;
                out[OFF_AP + bt*16 + la] = dot32(Cn + la*36, zn);
            }
            BAR1;
        }
    } else if (wid == 6){
        // warp 6: register Cholesky of CH, stores L directly
        for (int t = 0; t < TT; t++){
            BAR3;
            const float* CHc = CHd[t&1];
            float a[32];
            #pragma unroll
            for (int c = 0; c < 8; c++){
                float4 v = *(const float4*)(CHc + lane*36 + c*4);
                a[c*4] = v.x; a[c*4+1] = v.y; a[c*4+2] = v.z; a[c*4+3] = v.w;
            }
            float* o = out + OFF_LT + ((size_t)b*TT + t)*1024 + lane*32;
            #pragma unroll
            for (int j = 0; j < 32; j++){
                float d = __shfl_sync(0xffffffffu, a[j], j);
                float lij = a[j] * rsqrtf(d);
                o[j] = (lane >= j) ? lij : 0.f;
                #pragma unroll
                for (int k = j+1; k < 32; k++)
                    a[k] -= lij * __shfl_sync(0xffffffffu, lij, k);
            }
        }
    } else {
        // warp 7: GJ on [S | r | CP] -> Wb = Sinv*CP, srv = Sinv*r
        for (int t = 0; t < TT; t++){
            BAR2;
            float c[16], d[16];
            #pragma unroll
            for (int i = 0; i < 16; i++){
                c[i] = (lane < 16) ? SG[i*20 + lane] : ((lane == 16) ? rvec[i] : 0.f);
                d[i] = CP[i*36 + lane];
            }
            #pragma unroll
            for (int p = 0; p < 16; p++){
                float piv = __shfl_sync(0xffffffffu, c[p], p);
                float inv = __fdividef(1.0f, piv);
                float pc = c[p]*inv, pd = d[p]*inv;
                #pragma unroll
                for (int i = 0; i < 16; i++){
                    if (i == p) continue;
                    float fc = __shfl_sync(0xffffffffu, c[i], p);
                    c[i] -= fc*pc; d[i] -= fc*pd;
                }
                c[p] = pc; d[p] = pd;
            }
            #pragma unroll
            for (int i = 0; i < 16; i++) Wb[i*36 + lane] = d[i];
            if (lane == 16){
                #pragma unroll
                for (int i = 0; i < 16; i++) srv[i] = c[i];
            }
            BAR2;
        }
    }

    __syncthreads();
    // epilogue: PF/PP for t = 127
    const size_t bl = (size_t)b*TT + 127;
    {
        int e = tid*4, i = e >> 5, j = e & 31;
        *(float4*)(out + OFF_PF + bl*1024 + e) = *(const float4*)&Pf[i*36 + j];
        *(float4*)(out + OFF_PP + bl*1024 + e) = *(const float4*)&P[i*36 + j];
    }
}

extern "C" void kernel_launch(void* const* d_in, const int* in_sizes, int n_in,
                              void* d_out, int out_size) {
    const float* a_seq = (const float*)d_in[0];
    const float* h_obs = (const float*)d_in[1];
    const float* Amat  = (const float*)d_in[2];
    const float* Cmat  = (const float*)d_in[3];
    const float* a0    = (const float*)d_in[4];
    const float* Wx    = (const float*)d_in[5];
    const float* Wh    = (const float*)d_in[6];
    const float* bb    = (const float*)d_in[7];
    const float* Wo    = (const float*)d_in[8];
    const float* bo    = (const float*)d_in[9];
    float* out = (float*)d_out;

    gru_kernel<<<NB, 192>>>(a_seq, h_obs, a0, Wx, Wh, bb, Wo, bo, out);
    mix_kernel<<<dim3(NB, 129), 192>>>(Amat, Cmat, out);
    kf_kernel<<<NB, 256>>>(a_seq, out);
}